// round 12
// baseline (speedup 1.0000x reference)
#include <cuda_runtime.h>

// Problem constants (fixed by the dataset problem)
#define BB 2
#define CC 8
#define HH 128
#define WW 128
// patch P=3 -> d=72, window Wn=7 -> n=49

typedef unsigned long long ull;

// Scratch: phi0 = W_phi @ pan, g = W_g @ u, stored [b][y][x][c] as 2x float4 per pixel
__device__ float4 phi0_buf[BB * HH * WW * 2];
__device__ float4 g_buf[BB * HH * WW * 2];

// ---------- packed f32x2 helpers (sm_103a) ----------
__device__ __forceinline__ ull ffma2(ull a, ull b, ull c) {
    ull d;
    asm("fma.rn.f32x2 %0, %1, %2, %3;" : "=l"(d) : "l"(a), "l"(b), "l"(c));
    return d;
}
__device__ __forceinline__ ull fmul2(ull a, ull b) {
    ull d;
    asm("mul.rn.f32x2 %0, %1, %2;" : "=l"(d) : "l"(a), "l"(b));
    return d;
}
__device__ __forceinline__ float2 unpack2(ull v) {
    float2 r;
    asm("mov.b64 {%0, %1}, %2;" : "=f"(r.x), "=f"(r.y) : "l"(v));
    return r;
}
__device__ __forceinline__ ull pack2(float x, float y) {
    ull v;
    asm("mov.b64 %0, {%1, %2};" : "=l"(v) : "f"(x), "f"(y));
    return v;
}

__global__ void precompute_kernel(const float* __restrict__ u,
                                  const float* __restrict__ pan,
                                  const float* __restrict__ Wphi,
                                  const float* __restrict__ Wg) {
    __shared__ float sW[128];  // [0:64) = Wphi, [64:128) = Wg
    int tid = threadIdx.x;
    if (tid < 64) sW[tid] = Wphi[tid];
    else if (tid < 128) sW[tid] = Wg[tid - 64];
    __syncthreads();

    int idx = blockIdx.x * blockDim.x + tid;  // pixel index over b*h*w
    if (idx >= BB * HH * WW) return;
    int b = idx >> 14;            // / (128*128)
    int pix = idx & (HH * WW - 1);

    const float* pb = pan + b * CC * HH * WW + pix;
    const float* ub = u + b * CC * HH * WW + pix;
    float pv[8], uv[8];
#pragma unroll
    for (int i = 0; i < 8; i++) {
        pv[i] = pb[i * HH * WW];
        uv[i] = ub[i * HH * WW];
    }
    float po[8], go[8];
#pragma unroll
    for (int c = 0; c < 8; c++) {
        float a = 0.f, g = 0.f;
#pragma unroll
        for (int i = 0; i < 8; i++) {
            a += sW[c * 8 + i] * pv[i];
            g += sW[64 + c * 8 + i] * uv[i];
        }
        po[c] = a;
        go[c] = g;
    }
    phi0_buf[idx * 2 + 0] = make_float4(po[0], po[1], po[2], po[3]);
    phi0_buf[idx * 2 + 1] = make_float4(po[4], po[5], po[6], po[7]);
    g_buf[idx * 2 + 0]    = make_float4(go[0], go[1], go[2], go[3]);
    g_buf[idx * 2 + 1]    = make_float4(go[4], go[5], go[6], go[7]);
}

// One block = 16x16 output tile. Decomposed scoring:
//   logit(y,x,dy,dx) = sum_{i,j in 3x3} S(y+i-1, x+j-1, dy, dx)
//   S(y',x',dy,dx)   = <phi0_pad(y',x'), phi0_pad(y'+dy, x'+dx)>   (channel dot)
// with logit forced to 0 when the window target (y+dy,x+dx) is out of image
// (the outer unfold zero-pads whole descriptors).
// Window loop batched by row dy; one iteration handles all 7 dx.
// Warp->row map: warp w covers output rows (rowA, rowA+4) so scalar sS reads hit
// disjoint bank halves (4*20 = 80 = 16 mod 32) -> conflict-free.
__global__ __launch_bounds__(256) void attn_kernel(float* __restrict__ out) {
    // phi0 tile with halo 4: 24x24 positions, two float4 channel-planes
    __shared__ float4 sPhi0[576];  // channels 0-3, pos = r*24+q
    __shared__ float4 sPhi1[576];  // channels 4-7
    // g tile with halo 3: 22x22 positions
    __shared__ float4 sG0[484];
    __shared__ float4 sG1[484];
    // S buffers: one 18x18 region (row stride 20) per dx offset
    __shared__ float sS[7][18 * 20];

    const int b = blockIdx.z;
    const int ty0 = blockIdx.y * 16;
    const int tx0 = blockIdx.x * 16;
    const int tid = threadIdx.x;

    // warp->row remap for conflict-free box-sum LDS
    const int w = tid >> 5, lane = tid & 31;
    const int tx = lane & 15;
    const int rowA = (w < 4) ? w : (w + 4);      // warps 0-3 -> rows 0-3, 4-7 -> 8-11
    const int ty = rowA + ((lane >> 4) << 2);    // + 4 for upper half-warp

    // ---- load phi0 tile (halo 4, zero pad OOB) ----
    for (int i = tid; i < 576 * 2; i += 256) {
        int half = i & 1;
        int pos = i >> 1;
        int r = pos / 24, q = pos - r * 24;
        int gy = ty0 - 4 + r, gx = tx0 - 4 + q;
        float4 v = make_float4(0.f, 0.f, 0.f, 0.f);
        if ((unsigned)gy < HH && (unsigned)gx < WW)
            v = phi0_buf[(b * HH * WW + gy * WW + gx) * 2 + half];
        if (half == 0) sPhi0[pos] = v; else sPhi1[pos] = v;
    }
    // ---- load g tile (halo 3, zero pad OOB) ----
    for (int i = tid; i < 484 * 2; i += 256) {
        int half = i & 1;
        int pos = i >> 1;
        int r = pos / 22, q = pos - r * 22;
        int gy = ty0 - 3 + r, gx = tx0 - 3 + q;
        float4 v = make_float4(0.f, 0.f, 0.f, 0.f);
        if ((unsigned)gy < HH && (unsigned)gx < WW)
            v = g_buf[(b * HH * WW + gy * WW + gx) * 2 + half];
        if (half == 0) sG0[pos] = v; else sG1[pos] = v;
    }

    // ---- per-thread S work items (fixed across all window offsets) ----
    // S region: 18x18 items; item k -> (r = k/18, q = k%18), phi pos (3+r, 3+q)
    const int r0 = tid / 18, q0 = tid - r0 * 18;
    const int p0 = (3 + r0) * 24 + (3 + q0);
    const int i1 = tid + 256;
    const bool has1 = (i1 < 324);
    const int r1 = has1 ? (i1 / 18) : r0;
    const int q1 = has1 ? (i1 - (i1 / 18) * 18) : q0;
    const int p1 = (3 + r1) * 24 + (3 + q1);

    __syncthreads();  // tiles ready

    // center descriptors as packed f32x2 pairs
    const ulonglong2 c0a = *reinterpret_cast<const ulonglong2*>(&sPhi0[p0]);
    const ulonglong2 c0b = *reinterpret_cast<const ulonglong2*>(&sPhi1[p0]);
    const ulonglong2 c1a = *reinterpret_cast<const ulonglong2*>(&sPhi0[p1]);
    const ulonglong2 c1b = *reinterpret_cast<const ulonglong2*>(&sPhi1[p1]);

    const int py = ty0 + ty;
    const int px = tx0 + tx;

    float m = -1e30f, denom = 0.f;
    ull acc0 = 0ull, acc1 = 0ull, acc2 = 0ull, acc3 = 0ull;  // 8 channels packed

#pragma unroll 1
    for (int dy = -3; dy <= 3; dy++) {
        // ---- compute S for all 7 dx over the 18x18 region ----
        {
            const int sp0 = p0 + dy * 24 - 3;
            const int d0 = r0 * 20 + q0;
#pragma unroll
            for (int t = 0; t < 7; t++) {
                const ulonglong2 na = *reinterpret_cast<const ulonglong2*>(&sPhi0[sp0 + t]);
                const ulonglong2 nb = *reinterpret_cast<const ulonglong2*>(&sPhi1[sp0 + t]);
                ull acc = ffma2(c0a.x, na.x,
                          ffma2(c0a.y, na.y,
                          ffma2(c0b.x, nb.x,
                          fmul2(c0b.y, nb.y))));
                float2 f = unpack2(acc);
                sS[t][d0] = f.x + f.y;
            }
            if (has1) {
                const int sp1 = p1 + dy * 24 - 3;
                const int d1 = r1 * 20 + q1;
#pragma unroll
                for (int t = 0; t < 7; t++) {
                    const ulonglong2 na = *reinterpret_cast<const ulonglong2*>(&sPhi0[sp1 + t]);
                    const ulonglong2 nb = *reinterpret_cast<const ulonglong2*>(&sPhi1[sp1 + t]);
                    ull acc = ffma2(c1a.x, na.x,
                              ffma2(c1a.y, na.y,
                              ffma2(c1b.x, nb.x,
                              fmul2(c1b.y, nb.y))));
                    float2 f = unpack2(acc);
                    sS[t][d1] = f.x + f.y;
                }
            }
        }
        __syncthreads();

        // ---- 7 box-sums -> logits (0 if window target OOB) ----
        const bool rowOK = (unsigned)(py + dy) < HH;
        const int base = ty * 20 + tx;
        float s[7];
#pragma unroll
        for (int t = 0; t < 7; t++) {
            float v = 0.f;
            if (rowOK && (unsigned)(px + t - 3) < WW) {
                const float* Sb = sS[t];
                v = (Sb[base +  0] + Sb[base +  1]) + (Sb[base +  2] +
                     Sb[base + 20]) + (Sb[base + 21] + Sb[base + 22]) +
                    (Sb[base + 40] + Sb[base + 41]) + Sb[base + 42];
            }
            s[t] = v;
        }

        // ---- online softmax over this row of 7 + fused weighted-g accum ----
        float mx = m;
#pragma unroll
        for (int t = 0; t < 7; t++) mx = fmaxf(mx, s[t]);
        const float f = __expf(m - mx);
        const ull pf = pack2(f, f);
        denom *= f;
        acc0 = fmul2(pf, acc0);
        acc1 = fmul2(pf, acc1);
        acc2 = fmul2(pf, acc2);
        acc3 = fmul2(pf, acc3);

        const int gbase = (3 + ty + dy) * 22 + tx;  // col: (3 + tx - 3) + t = tx + t
        float wv[7];
#pragma unroll
        for (int t = 0; t < 7; t++) {
            wv[t] = __expf(s[t] - mx);
            const ull pw = pack2(wv[t], wv[t]);
            const ulonglong2 ga = *reinterpret_cast<const ulonglong2*>(&sG0[gbase + t]);
            const ulonglong2 gb = *reinterpret_cast<const ulonglong2*>(&sG1[gbase + t]);
            acc0 = ffma2(pw, ga.x, acc0);
            acc1 = ffma2(pw, ga.y, acc1);
            acc2 = ffma2(pw, gb.x, acc2);
            acc3 = ffma2(pw, gb.y, acc3);
        }
        // tree-sum the 7 weights to avoid a serial FADD chain
        denom += ((wv[0] + wv[1]) + (wv[2] + wv[3])) + ((wv[4] + wv[5]) + wv[6]);
        m = mx;
        __syncthreads();  // readers of sS done before next row overwrites
    }

    const float inv = 1.f / denom;
    const float2 a0 = unpack2(acc0), a1 = unpack2(acc1);
    const float2 a2 = unpack2(acc2), a3 = unpack2(acc3);
    // output layout: (b, uc, 1, h, w) == contiguous (b, uc, h, w)
    float* ob = out + (b * CC) * (HH * WW) + py * WW + px;
    ob[0 * HH * WW] = a0.x * inv;
    ob[1 * HH * WW] = a0.y * inv;
    ob[2 * HH * WW] = a1.x * inv;
    ob[3 * HH * WW] = a1.y * inv;
    ob[4 * HH * WW] = a2.x * inv;
    ob[5 * HH * WW] = a2.y * inv;
    ob[6 * HH * WW] = a3.x * inv;
    ob[7 * HH * WW] = a3.y * inv;
}

extern "C" void kernel_launch(void* const* d_in, const int* in_sizes, int n_in,
                              void* d_out, int out_size) {
    const float* u    = (const float*)d_in[0];
    const float* pan  = (const float*)d_in[1];
    const float* Wphi = (const float*)d_in[2];
    const float* Wg   = (const float*)d_in[3];
    float* out = (float*)d_out;

    // phase 1: 1x1 convs into channel-contiguous scratch
    precompute_kernel<<<(BB * HH * WW + 255) / 256, 256>>>(u, pan, Wphi, Wg);

    // phase 2: fused window attention
    dim3 grid(WW / 16, HH / 16, BB);
    dim3 block(256, 1, 1);
    attn_kernel<<<grid, block>>>(out);
}